// round 14
// baseline (speedup 1.0000x reference)
#include <cuda_runtime.h>
#include <cstdint>

#define B_ 1024
#define T_ 256
#define D_ 64
#define H_ 128

// Precomputed x-projections (pre-activation, bias included).
__device__ float g_xg[(size_t)B_ * T_ * 256];   // gate: r cols 0..127, u cols 128..255
__device__ float g_xc[(size_t)B_ * T_ * 128];   // candidate
__device__ int   g_perm[B_];                    // rows sorted by len desc

// Transposed recurrent weights, L1-resident during phase B.
// g_wgT[col][k] = Wg[64+k][col]  (256 cols x 128 k)
// g_wcT[col][k] = Wc[64+k][col]  (128 cols x 128 k)
__device__ __align__(16) float g_wgT[256 * 128];
__device__ __align__(16) float g_wcT[128 * 128];

// ---- packed f32x2 helpers ----
__device__ __forceinline__ unsigned long long pack2(float lo, float hi) {
    unsigned long long r;
    asm("mov.b64 %0, {%1, %2};" : "=l"(r) : "f"(lo), "f"(hi));
    return r;
}
__device__ __forceinline__ void fma2(unsigned long long& acc,
                                     unsigned long long a,
                                     unsigned long long b) {
    asm("fma.rn.f32x2 %0, %1, %2, %0;" : "+l"(acc) : "l"(a), "l"(b));
}
__device__ __forceinline__ float sum2(unsigned long long a) {
    float lo, hi;
    asm("mov.b64 {%0, %1}, %2;" : "=f"(lo), "=f"(hi) : "l"(a));
    return lo + hi;
}
__device__ __forceinline__ float sigmoidf(float s) { return 1.f / (1.f + __expf(-s)); }
__device__ __forceinline__ float tanh_safe(float s) {
    const float sc = fminf(fmaxf(s, -15.f), 15.f);
    const float e  = __expf(2.f * sc);
    return (e - 1.f) / (e + 1.f);
}

// named-barrier producer/consumer sync (384 = all threads in CTA)
#define BSYNC(id)   asm volatile("bar.sync %0, 384;"   :: "r"(id) : "memory")
#define BARRIVE(id) asm volatile("bar.arrive %0, 384;" :: "r"(id) : "memory")

// ============================================================================
// Sort rows by seq_len descending (counting sort, one CTA).
// ============================================================================
__global__ void sort_rows(const int* __restrict__ seq_lens) {
    __shared__ int base[T_ + 1];
    const int tid = threadIdx.x;          // 1024 threads
    if (tid <= T_) base[tid] = 0;
    __syncthreads();
    const int len = seq_lens[tid];
    atomicAdd(&base[len], 1);
    __syncthreads();
    if (tid == 0) {                        // descending prefix
        int acc = 0;
        for (int l = T_; l >= 0; l--) { int c = base[l]; base[l] = acc; acc += c; }
    }
    __syncthreads();
    const int pos = atomicAdd(&base[len], 1);
    g_perm[pos] = tid;
}

// ============================================================================
// Transpose recurrent weights into [col][k] layout (k contiguous, 16B-aligned).
// ============================================================================
__global__ void prep_weights(const float* __restrict__ Wg,
                             const float* __restrict__ Wc) {
    const int idx = blockIdx.x * 256 + threadIdx.x;   // 128 blocks x 256 thr
    if (idx < 256 * 128) {
        const int col = idx >> 7, k = idx & 127;
        g_wgT[idx] = Wg[(64 + k) * 256 + col];
    }
    if (idx < 128 * 128) {
        const int col = idx >> 7, k = idx & 127;
        g_wcT[idx] = Wc[(64 + k) * 128 + col];
    }
}

// ============================================================================
// Phase A: time-parallel x-projections. Weights in regs, x via LDS.128.
// ============================================================================
__global__ __launch_bounds__(384)
void gru_phaseA(const int* __restrict__ item_his,
                const int* __restrict__ seq_lens,
                const float* __restrict__ emb,
                const float* __restrict__ Wg,
                const float* __restrict__ bg,
                const float* __restrict__ Wc,
                const float* __restrict__ bc)
{
    const int b  = blockIdx.y;
    const int t0 = blockIdx.x * 64;
    const int len = seq_lens[b];
    if (t0 >= len) return;
    const int nt = min(64, len - t0);
    const int tid = threadIdx.x;

    __shared__ int idx_sh[64];
    __shared__ __align__(16) float x_sh[64 * 64];

    unsigned long long wp[32];
    float bias;
    if (tid < 256) {
        bias = bg[tid];
#pragma unroll
        for (int i = 0; i < 32; i++)
            wp[i] = pack2(Wg[(2 * i) * 256 + tid], Wg[(2 * i + 1) * 256 + tid]);
    } else {
        const int c = tid - 256;
        bias = bc[c];
#pragma unroll
        for (int i = 0; i < 32; i++)
            wp[i] = pack2(Wc[(2 * i) * 128 + c], Wc[(2 * i + 1) * 128 + c]);
    }

    if (tid < nt) idx_sh[tid] = item_his[b * T_ + t0 + tid];
    __syncthreads();

    {   // coalesced gather: nt embedding rows of 256B each
        const float4* e4 = (const float4*)emb;
        float4* x4 = (float4*)x_sh;
        for (int i = tid; i < nt * 16; i += 384) {
            const int r = i >> 4, q = i & 15;
            x4[r * 16 + q] = e4[(size_t)idx_sh[r] * 16 + q];
        }
    }
    __syncthreads();

    const ulonglong2* x2 = (const ulonglong2*)x_sh;
    for (int r = 0; r < nt; r += 2) {
        const bool two = (r + 1 < nt);
        unsigned long long a0 = 0ULL, a1 = 0ULL, b0 = 0ULL, b1 = 0ULL;
#pragma unroll
        for (int i = 0; i < 16; i++) {
            ulonglong2 xx = x2[r * 16 + i];
            fma2(a0, xx.x, wp[2 * i]);
            fma2(a1, xx.y, wp[2 * i + 1]);
            if (two) {
                ulonglong2 yy = x2[(r + 1) * 16 + i];
                fma2(b0, yy.x, wp[2 * i]);
                fma2(b1, yy.y, wp[2 * i + 1]);
            }
        }
        const float acc0 = sum2(a0) + sum2(a1) + bias;
        const size_t p0 = (size_t)b * T_ + t0 + r;
        if (tid < 256) __stcs(&g_xg[p0 * 256 + tid], acc0);
        else           __stcs(&g_xc[p0 * 128 + (tid - 256)], acc0);
        if (two) {
            const float acc1 = sum2(b0) + sum2(b1) + bias;
            if (tid < 256) __stcs(&g_xg[(p0 + 1) * 256 + tid], acc1);
            else           __stcs(&g_xc[(p0 + 1) * 128 + (tid - 256)], acc1);
        }
    }
}

// ============================================================================
// Phase B: decoupled producer/consumer recurrence on length-sorted rows.
//   R5 skeleton (4 rows/CTA, A={0,1}, B={2,3}, 4 named barriers/step,
//   depth-2 x prefetch) but weights streamed from L1 (transposed global,
//   LDG.128) instead of register-resident -> low regs -> 2 CTAs/SM.
// ============================================================================
template<int NR>
__device__ __forceinline__ void dot2g(const ulonglong2* __restrict__ w2,
                                      const float* __restrict__ v0,
                                      const float* __restrict__ v1,
                                      float& s0, float& s1)
{
    const ulonglong2* p0 = (const ulonglong2*)v0;
    const ulonglong2* p1 = (const ulonglong2*)v1;
    unsigned long long a00 = 0ULL, a01 = 0ULL, a10 = 0ULL, a11 = 0ULL;
    // FIX (R13 bug): 128 floats = 32 ulonglong2 — loop must run 32x, not 16x.
#pragma unroll
    for (int i = 0; i < 32; i++) {
        const ulonglong2 w = w2[i];                 // LDG.128 (L1-hit)
        ulonglong2 x0 = p0[i];                      // LDS.128 broadcast
        fma2(a00, x0.x, w.x);
        fma2(a01, x0.y, w.y);
        if (NR == 2) {
            ulonglong2 x1 = p1[i];
            fma2(a10, x1.x, w.x);
            fma2(a11, x1.y, w.y);
        }
    }
    s0 = sum2(a00) + sum2(a01);
    if (NR == 2) s1 = sum2(a10) + sum2(a11);
}

__global__ __launch_bounds__(384, 2)
void gru_phaseB(const int* __restrict__ seq_lens,
                float* __restrict__ out)
{
    __shared__ __align__(16) float h[4][128];
    __shared__ __align__(16) float rh[4][128];
    __shared__ float uu[4][128];

    const int tid = threadIdx.x;
    const int cta = blockIdx.x;

    int bidx[4], len[4];
#pragma unroll
    for (int r = 0; r < 4; r++) {
        bidx[r] = g_perm[cta * 4 + r];                // sorted desc: l0>=l1>=l2>=l3
        len[r]  = seq_lens[bidx[r]];
    }
    const int tmax = len[0];
    if (tmax == 0) {
        for (int i = tid; i < 512; i += 384)
            out[bidx[i >> 7] * 128 + (i & 127)] = 0.f;
        return;
    }

    const bool isGate = tid < 256;
    const int  j      = isGate ? tid : tid - 256;

    // my weight column, k-contiguous, 16B-aligned: 32 x ulonglong2 (128 floats)
    const ulonglong2* w2 = (const ulonglong2*)
        (isGate ? (g_wgT + j * 128) : (g_wcT + j * 128));

    for (int i = tid; i < 512; i += 384) ((float*)h)[i] = 0.f;
    __syncthreads();

    // x prefetch (depth 2)
    auto xval = [&](int r, int tt) -> float {
        if (tt < len[r]) {
            if (isGate) return __ldcs(&g_xg[((size_t)bidx[r] * T_ + tt) * 256 + j]);
            else        return __ldcs(&g_xc[((size_t)bidx[r] * T_ + tt) * 128 + j]);
        }
        return 0.f;
    };
    float q0[4], q1[4], q2[4];
#pragma unroll
    for (int r = 0; r < 4; r++) { q0[r] = xval(r, 0); q1[r] = xval(r, 1); }

    // cand pre-arms the h-ready barriers (h zeroed + synced above)
    if (!isGate) { BARRIVE(1); BARRIVE(2); }

    for (int t = 0; t < tmax; t++) {
#pragma unroll
        for (int r = 0; r < 4; r++) q2[r] = xval(r, t + 2);

        if (isGate) {
            // ---- G_A(t): rows 0,1 ----
            BSYNC(1);
            {
                float s0, s1;
                if (t < len[1]) dot2g<2>(w2, h[0], h[1], s0, s1);
                else            dot2g<1>(w2, h[0], h[1], s0, s1);
                const float g0 = sigmoidf(s0 + q0[0]);
                if (j < 128) rh[0][j] = g0 * h[0][j]; else uu[0][j - 128] = g0;
                if (t < len[1]) {
                    const float g1 = sigmoidf(s1 + q0[1]);
                    if (j < 128) rh[1][j] = g1 * h[1][j]; else uu[1][j - 128] = g1;
                }
            }
            BARRIVE(3);
            // ---- G_B(t): rows 2,3 ----
            BSYNC(2);
            if (t < len[2]) {
                float s0, s1;
                if (t < len[3]) dot2g<2>(w2, h[2], h[3], s0, s1);
                else            dot2g<1>(w2, h[2], h[3], s0, s1);
                const float g0 = sigmoidf(s0 + q0[2]);
                if (j < 128) rh[2][j] = g0 * h[2][j]; else uu[2][j - 128] = g0;
                if (t < len[3]) {
                    const float g1 = sigmoidf(s1 + q0[3]);
                    if (j < 128) rh[3][j] = g1 * h[3][j]; else uu[3][j - 128] = g1;
                }
            }
            BARRIVE(4);
        } else {
            // ---- C_A(t): rows 0,1 ----
            BSYNC(3);
            {
                float s0, s1;
                if (t < len[1]) dot2g<2>(w2, rh[0], rh[1], s0, s1);
                else            dot2g<1>(w2, rh[0], rh[1], s0, s1);
                const float c0 = tanh_safe(s0 + q0[0]);
                const float u0 = uu[0][j];
                h[0][j] = u0 * h[0][j] + (1.f - u0) * c0;
                if (t < len[1]) {
                    const float c1 = tanh_safe(s1 + q0[1]);
                    const float u1 = uu[1][j];
                    h[1][j] = u1 * h[1][j] + (1.f - u1) * c1;
                }
            }
            if (t + 1 < tmax) BARRIVE(1);
            // ---- C_B(t): rows 2,3 ----
            BSYNC(4);
            if (t < len[2]) {
                float s0, s1;
                if (t < len[3]) dot2g<2>(w2, rh[2], rh[3], s0, s1);
                else            dot2g<1>(w2, rh[2], rh[3], s0, s1);
                const float c0 = tanh_safe(s0 + q0[2]);
                const float u0 = uu[2][j];
                h[2][j] = u0 * h[2][j] + (1.f - u0) * c0;
                if (t < len[3]) {
                    const float c1 = tanh_safe(s1 + q0[3]);
                    const float u1 = uu[3][j];
                    h[3][j] = u1 * h[3][j] + (1.f - u1) * c1;
                }
            }
            if (t + 1 < tmax) BARRIVE(2);
        }

#pragma unroll
        for (int r = 0; r < 4; r++) { q0[r] = q1[r]; q1[r] = q2[r]; }
    }

    __syncthreads();
    for (int i = tid; i < 512; i += 384)
        out[bidx[i >> 7] * 128 + (i & 127)] = ((float*)h)[i];
}

// ============================================================================
extern "C" void kernel_launch(void* const* d_in, const int* in_sizes, int n_in,
                              void* d_out, int out_size)
{
    const int*   item_his = (const int*)d_in[0];
    const int*   seq_lens = (const int*)d_in[1];
    const float* emb      = (const float*)d_in[2];
    const float* Wg       = (const float*)d_in[3];
    const float* bg       = (const float*)d_in[4];
    const float* Wc       = (const float*)d_in[5];
    const float* bc       = (const float*)d_in[6];
    float* out = (float*)d_out;

    sort_rows<<<1, B_>>>(seq_lens);
    prep_weights<<<128, 256>>>(Wg, Wc);
    dim3 gA(T_ / 64, B_);   // (4, 1024)
    gru_phaseA<<<gA, 384>>>(item_his, seq_lens, emb, Wg, bg, Wc, bc);
    gru_phaseB<<<B_ / 4, 384>>>(seq_lens, out);
}